// round 5
// baseline (speedup 1.0000x reference)
#include <cuda_runtime.h>
#include <cstdint>

// LSTM: B=2048, T=4096, I=5, H=10. Gate order i,f,g,o (rows of W_ih/W_hh).
//   gates = x @ W_ih^T + b_ih + b_hh + h @ W_hh^T
//   c = sigmoid(f)*c + sigmoid(i)*tanh(g);  h = sigmoid(o)*tanh(c)
//
// Parallelization: one thread per (batch, hidden unit j). 10-lane groups,
// 3 batches per warp (lanes 0..29). h exchanged via warp shuffles.
// Packed f32x2 FMA (sm_10x) for gate pairs (i,f) and (g,o).

#define BB 2048
#define TT 4096
#define II 5
#define HH 10

typedef unsigned long long u64;

static __device__ __forceinline__ u64 pk2(float a, float b) {
    u64 r;
    asm("mov.b64 %0, {%1, %2};" : "=l"(r) : "f"(a), "f"(b));
    return r;
}
static __device__ __forceinline__ void upk2(u64 v, float& a, float& b) {
    asm("mov.b64 {%0, %1}, %2;" : "=f"(a), "=f"(b) : "l"(v));
}
static __device__ __forceinline__ u64 ffma2(u64 a, u64 b, u64 c) {
    u64 d;
    asm("fma.rn.f32x2 %0, %1, %2, %3;" : "=l"(d) : "l"(a), "l"(b), "l"(c));
    return d;
}
static __device__ __forceinline__ u64 fadd2(u64 a, u64 b) {
    u64 d;
    asm("add.rn.f32x2 %0, %1, %2;" : "=l"(d) : "l"(a), "l"(b));
    return d;
}

// sigmoid via ex2.approx + rcp.approx (both ~2^-22 accurate).
// Saturates correctly at +/-inf through rcp(inf)=0.
static __device__ __forceinline__ float sigm(float x) {
    float e = __expf(-x);
    return __fdividef(1.0f, 1.0f + e);
}
// tanh(x) = 1 - 2/(e^{2x}+1); stable at both tails.
static __device__ __forceinline__ float tanh_fast(float x) {
    float e = __expf(2.0f * x);
    return 1.0f - __fdividef(2.0f, e + 1.0f);
}

__global__ void __launch_bounds__(32)
lstm_scan_kernel(const float* __restrict__ x,
                 const float* __restrict__ h0,
                 const float* __restrict__ c0,
                 const float* __restrict__ W_ih,
                 const float* __restrict__ W_hh,
                 const float* __restrict__ b_ih,
                 const float* __restrict__ b_hh,
                 float* __restrict__ out)
{
    const int lane = threadIdx.x;
    const int group = (lane < 30) ? (lane / 10) : 0;
    const int j     = (lane < 30) ? (lane - group * 10) : 0;
    const int gbase = group * 10;

    int b = blockIdx.x * 3 + group;
    const bool active = (lane < 30) && (b < BB);
    if (b >= BB) b = 0;  // clamp for safe (redundant) loads; store is guarded

    // Gate rows for this hidden unit.
    const int ri = j, rf = HH + j, rg = 2 * HH + j, ro = 3 * HH + j;

    // Register-resident packed weights: (i,f) pair and (g,o) pair.
    u64 wih_if[II], wih_go[II], whh_if[HH], whh_go[HH];
#pragma unroll
    for (int i = 0; i < II; i++) {
        wih_if[i] = pk2(W_ih[ri * II + i], W_ih[rf * II + i]);
        wih_go[i] = pk2(W_ih[rg * II + i], W_ih[ro * II + i]);
    }
#pragma unroll
    for (int k = 0; k < HH; k++) {
        whh_if[k] = pk2(W_hh[ri * HH + k], W_hh[rf * HH + k]);
        whh_go[k] = pk2(W_hh[rg * HH + k], W_hh[ro * HH + k]);
    }
    const u64 bias_if = pk2(b_ih[ri] + b_hh[ri], b_ih[rf] + b_hh[rf]);
    const u64 bias_go = pk2(b_ih[rg] + b_hh[rg], b_ih[ro] + b_hh[ro]);

    float h = h0[b * HH + j];
    float c = c0[b * HH + j];

    const float* xb = x + (size_t)b * TT * II;
    float* ob = out + (size_t)b * TT * HH + j;

    // Prefetch x for t=0.
    float xn[II];
#pragma unroll
    for (int i = 0; i < II; i++) xn[i] = xb[i];

#pragma unroll 1
    for (int t = 0; t < TT; ++t) {
        float xc[II];
#pragma unroll
        for (int i = 0; i < II; i++) xc[i] = xn[i];

        // Prefetch next step's x (independent of the recurrent chain).
        {
            const int tn = (t + 1 < TT) ? (t + 1) : t;
            const float* xp = xb + tn * II;
#pragma unroll
            for (int i = 0; i < II; i++) xn[i] = xp[i];
        }

        // Split accumulators (even/odd) to shorten the serial FMA chain.
        u64 aif0 = bias_if, aif1 = 0ull;  // 0ull == {0.0f, 0.0f}
        u64 ago0 = bias_go, ago1 = 0ull;

        // Input contribution (off the recurrent critical path).
#pragma unroll
        for (int i = 0; i < II; i++) {
            u64 xx = pk2(xc[i], xc[i]);
            if (i & 1) {
                aif1 = ffma2(wih_if[i], xx, aif1);
                ago1 = ffma2(wih_go[i], xx, ago1);
            } else {
                aif0 = ffma2(wih_if[i], xx, aif0);
                ago0 = ffma2(wih_go[i], xx, ago0);
            }
        }

        // Recurrent contribution: broadcast h across the 10-lane group.
#pragma unroll
        for (int k = 0; k < HH; k++) {
            float hk = __shfl_sync(0xFFFFFFFFu, h, gbase + k);
            u64 hh = pk2(hk, hk);
            if (k & 1) {
                aif1 = ffma2(whh_if[k], hh, aif1);
                ago1 = ffma2(whh_go[k], hh, ago1);
            } else {
                aif0 = ffma2(whh_if[k], hh, aif0);
                ago0 = ffma2(whh_go[k], hh, ago0);
            }
        }

        u64 aif = fadd2(aif0, aif1);
        u64 ago = fadd2(ago0, ago1);
        float ai, af, ag, ao;
        upk2(aif, ai, af);
        upk2(ago, ag, ao);

        const float ig = sigm(ai);
        const float fg = sigm(af);
        const float gg = tanh_fast(ag);
        const float og = sigm(ao);

        c = fmaf(fg, c, ig * gg);
        h = og * tanh_fast(c);

        if (active) ob[(size_t)t * HH] = h;
    }
}

extern "C" void kernel_launch(void* const* d_in, const int* in_sizes, int n_in,
                              void* d_out, int out_size) {
    (void)in_sizes; (void)n_in; (void)out_size;
    const float* x    = (const float*)d_in[0];
    const float* h0   = (const float*)d_in[1];
    const float* c0   = (const float*)d_in[2];
    const float* W_ih = (const float*)d_in[3];
    const float* W_hh = (const float*)d_in[4];
    const float* b_ih = (const float*)d_in[5];
    const float* b_hh = (const float*)d_in[6];
    float* out = (float*)d_out;

    const int nwarps = (BB + 2) / 3;  // 3 batches per warp
    lstm_scan_kernel<<<nwarps, 32>>>(x, h0, c0, W_ih, W_hh, b_ih, b_hh, out);
}

// round 7
// speedup vs baseline: 1.1545x; 1.1545x over previous
#include <cuda_runtime.h>
#include <cstdint>

// LSTM: B=2048, T=4096, I=5, H=10. Gate order i,f,g,o (rows of W_ih/W_hh).
//   gates = x @ W_ih^T + b_ih + b_hh + h @ W_hh^T
//   c = sigmoid(f)*c + sigmoid(i)*tanh(g);  h = sigmoid(o)*tanh(c)
//
// One thread per (batch, hidden unit j); 10-lane groups, 3 batches/warp.
// h exchanged via warp shuffles. Packed f32x2 FMA for gate pairs (i,f),(g,o).
// Activations via MUFU.TANH (tanh.approx.f32); sigmoid(x)=0.5+0.5*tanh(x/2)
// with the x/2 folded into pre-scaled weights/biases.

#define BB 2048
#define TT 4096
#define II 5
#define HH 10

typedef unsigned long long u64;

static __device__ __forceinline__ u64 pk2(float a, float b) {
    u64 r;
    asm("mov.b64 %0, {%1, %2};" : "=l"(r) : "f"(a), "f"(b));
    return r;
}
static __device__ __forceinline__ void upk2(u64 v, float& a, float& b) {
    asm("mov.b64 {%0, %1}, %2;" : "=f"(a), "=f"(b) : "l"(v));
}
static __device__ __forceinline__ u64 ffma2(u64 a, u64 b, u64 c) {
    u64 d;
    asm("fma.rn.f32x2 %0, %1, %2, %3;" : "=l"(d) : "l"(a), "l"(b), "l"(c));
    return d;
}
static __device__ __forceinline__ u64 fadd2(u64 a, u64 b) {
    u64 d;
    asm("add.rn.f32x2 %0, %1, %2;" : "=l"(d) : "l"(a), "l"(b));
    return d;
}
// Single-MUFU tanh (MUFU.TANH), sm_75+.
static __device__ __forceinline__ float tanh_x(float x) {
    float y;
    asm("tanh.approx.f32 %0, %1;" : "=f"(y) : "f"(x));
    return y;
}

__global__ void __launch_bounds__(32)
lstm_scan_kernel(const float* __restrict__ x,
                 const float* __restrict__ h0,
                 const float* __restrict__ c0,
                 const float* __restrict__ W_ih,
                 const float* __restrict__ W_hh,
                 const float* __restrict__ b_ih,
                 const float* __restrict__ b_hh,
                 float* __restrict__ out)
{
    const int lane = threadIdx.x;
    const int group = (lane < 30) ? (lane / 10) : 0;
    const int j     = (lane < 30) ? (lane - group * 10) : 0;
    const int gbase = group * 10;

    int b = blockIdx.x * 3 + group;
    const bool active = (lane < 30) && (b < BB);
    if (b >= BB) b = 0;  // clamp for safe (redundant) loads; store is guarded

    // Gate rows for this hidden unit.
    const int ri = j, rf = HH + j, rg = 2 * HH + j, ro = 3 * HH + j;

    // Register-resident packed weights. Sigmoid gates (i,f,o) are pre-scaled
    // by 0.5 so sigmoid(x) = 0.5 + 0.5*tanh(acc) with no extra multiply.
    u64 wih_if[II], wih_go[II], whh_if[HH], whh_go[HH];
#pragma unroll
    for (int i = 0; i < II; i++) {
        wih_if[i] = pk2(0.5f * W_ih[ri * II + i], 0.5f * W_ih[rf * II + i]);
        wih_go[i] = pk2(       W_ih[rg * II + i], 0.5f * W_ih[ro * II + i]);
    }
#pragma unroll
    for (int k = 0; k < HH; k++) {
        whh_if[k] = pk2(0.5f * W_hh[ri * HH + k], 0.5f * W_hh[rf * HH + k]);
        whh_go[k] = pk2(       W_hh[rg * HH + k], 0.5f * W_hh[ro * HH + k]);
    }
    const u64 bias_if = pk2(0.5f * (b_ih[ri] + b_hh[ri]),
                            0.5f * (b_ih[rf] + b_hh[rf]));
    const u64 bias_go = pk2(        b_ih[rg] + b_hh[rg],
                            0.5f * (b_ih[ro] + b_hh[ro]));

    float h = h0[b * HH + j];
    float c = c0[b * HH + j];

    const float* xb = x + (size_t)b * TT * II;
    float* ob = out + (size_t)b * TT * HH + j;

    // Prefetch x for t=0.
    float xn[II];
#pragma unroll
    for (int i = 0; i < II; i++) xn[i] = xb[i];

#pragma unroll 1
    for (int t = 0; t < TT; ++t) {
        float xc[II];
#pragma unroll
        for (int i = 0; i < II; i++) xc[i] = xn[i];

        // Prefetch next step's x (independent of the recurrent chain).
        {
            const int tn = (t + 1 < TT) ? (t + 1) : t;
            const float* xp = xb + tn * II;
#pragma unroll
            for (int i = 0; i < II; i++) xn[i] = xp[i];
        }

        // Split accumulators (even/odd) to shorten the serial FMA chain.
        u64 aif0 = bias_if, aif1 = 0ull;  // 0ull == {0.0f, 0.0f}
        u64 ago0 = bias_go, ago1 = 0ull;

        // Input contribution (off the recurrent critical path).
#pragma unroll
        for (int i = 0; i < II; i++) {
            u64 xx = pk2(xc[i], xc[i]);
            if (i & 1) {
                aif1 = ffma2(wih_if[i], xx, aif1);
                ago1 = ffma2(wih_go[i], xx, ago1);
            } else {
                aif0 = ffma2(wih_if[i], xx, aif0);
                ago0 = ffma2(wih_go[i], xx, ago0);
            }
        }

        // Recurrent contribution: broadcast h across the 10-lane group.
#pragma unroll
        for (int k = 0; k < HH; k++) {
            float hk = __shfl_sync(0xFFFFFFFFu, h, gbase + k);
            u64 hh = pk2(hk, hk);
            if (k & 1) {
                aif1 = ffma2(whh_if[k], hh, aif1);
                ago1 = ffma2(whh_go[k], hh, ago1);
            } else {
                aif0 = ffma2(whh_if[k], hh, aif0);
                ago0 = ffma2(whh_go[k], hh, ago0);
            }
        }

        u64 aif = fadd2(aif0, aif1);
        u64 ago = fadd2(ago0, ago1);
        float ai, af, ag, ao;
        upk2(aif, ai, af);   // pre-scaled by 0.5 (sigmoid args)
        upk2(ago, ag, ao);   // ag unscaled (tanh), ao pre-scaled

        // f-gate first: it heads the critical c -> tanh(c) -> h chain.
        const float fg = fmaf(0.5f, tanh_x(af), 0.5f);
        const float ig = fmaf(0.5f, tanh_x(ai), 0.5f);
        const float gg = tanh_x(ag);
        const float og = fmaf(0.5f, tanh_x(ao), 0.5f);

        c = fmaf(fg, c, ig * gg);
        h = og * tanh_x(c);

        if (active) ob[(size_t)t * HH] = h;
    }
}

extern "C" void kernel_launch(void* const* d_in, const int* in_sizes, int n_in,
                              void* d_out, int out_size) {
    (void)in_sizes; (void)n_in; (void)out_size;
    const float* x    = (const float*)d_in[0];
    const float* h0   = (const float*)d_in[1];
    const float* c0   = (const float*)d_in[2];
    const float* W_ih = (const float*)d_in[3];
    const float* W_hh = (const float*)d_in[4];
    const float* b_ih = (const float*)d_in[5];
    const float* b_hh = (const float*)d_in[6];
    float* out = (float*)d_out;

    const int nwarps = (BB + 2) / 3;  // 3 batches per warp
    lstm_scan_kernel<<<nwarps, 32>>>(x, h0, c0, W_ih, W_hh, b_ih, b_hh, out);
}